// round 16
// baseline (speedup 1.0000x reference)
#include <cuda_runtime.h>
#include <math.h>
#include <stdint.h>
#include <stddef.h>

#define NRAYS 2048
#define NSAMP 128
#define NS (NRAYS * NSAMP)   // 262144 samples per pass

// ---------------- static scratch (no allocations allowed) ----------------
__device__ float g_enc[NRAYS * 96 * 128];   // block-transposed IPE: [ray][k][m]
__device__ float g_rf[NS * 6];              // raw heads per sample
__device__ float g_direnc[NRAYS * 27];
__device__ float g_raynorm[NRAYS];
__device__ float g_raybias[NRAYS * 128];
__device__ float g_weights[NS];
__device__ float g_mus[NS];
__device__ float g_smsig[NS];
__device__ float g_lt[NS];
__device__ float g_pib[NS];
__device__ float g_tfine[NRAYS * 129];
__device__ float g_cdf[NRAYS * 129];
__device__ float g_pdfn[NS];

// packed-weight scratch: per network, layers at fixed offsets (u32 words)
//   W0: 48x256=12288 | Wh0/1/2: 128x256=32768 each | Wb: 32768 | Wd: 128x128=16384
#define OFF_W0 0
#define OFF_WH 12288
#define OFF_WB 110592
#define OFF_WD 143360
#define WPK_TOTAL 159744
__device__ uint32_t g_wpkH[2][WPK_TOTAL];
__device__ uint32_t g_wpkL[2][WPK_TOTAL];

// fused-kernel smem layout:
//   act  : 256 x 132 fp32                      (135168 B)
//   BpkH : 3 buf x 8 k2 x 264 u32 (bf16x2)     ( 25344 B)
//   BpkL : same                                ( 25344 B)
#define ACT_STRIDE 132
#define ACT_WORDS (256 * ACT_STRIDE)
#define BPK_WORDS (3 * 8 * 264)
#define FUSED_SMEM ((ACT_WORDS + 2 * BPK_WORDS) * 4)   // 185856 B

// ---------------- helpers ----------------
__device__ __forceinline__ float fast_sigmoid(float x) {
    return 1.0f / (1.0f + __expf(-x));
}
__device__ __forceinline__ float acdf_(float x) {
    float x3 = x * x * x;
    float z = 0.7978845608028654f * (x + 0.044715f * x3);
    return 1.0f / (1.0f + __expf(-2.0f * z));
}
// pack {lower = bf16(x0) [k even], upper = bf16(x1) [k odd]}
__device__ __forceinline__ uint32_t pack_bf16x2(float x0, float x1) {
    uint32_t d;
    asm("cvt.rn.bf16x2.f32 %0, %1, %2;" : "=r"(d) : "f"(x1), "f"(x0));
    return d;
}
__device__ __forceinline__ void split_pair(float x0, float x1, uint32_t& hpk, uint32_t& lpk) {
    hpk = pack_bf16x2(x0, x1);
    float h0 = __uint_as_float(hpk << 16);
    float h1 = __uint_as_float(hpk & 0xffff0000u);
    lpk = pack_bf16x2(x0 - h0, x1 - h1);
}
__device__ __forceinline__ void cp16(void* s, const void* g) {
    uint32_t sa = (uint32_t)__cvta_generic_to_shared(s);
    asm volatile("cp.async.ca.shared.global [%0], [%1], 16;" :: "r"(sa), "l"(g));
}
__device__ __forceinline__ void cp8(void* s, const void* g) {
    uint32_t sa = (uint32_t)__cvta_generic_to_shared(s);
    asm volatile("cp.async.ca.shared.global [%0], [%1], 8;" :: "r"(sa), "l"(g));
}
__device__ __forceinline__ void cp_commit() {
    asm volatile("cp.async.commit_group;" ::: "memory");
}
__device__ __forceinline__ void cp_wait0() {
    asm volatile("cp.async.wait_group 0;" ::: "memory");
}
__device__ __forceinline__ void cp_wait1() {
    asm volatile("cp.async.wait_group 1;" ::: "memory");
}

#define MMA_BF16(d, a0, a1, a2, a3, b0, b1)                                  \
    asm volatile(                                                            \
        "mma.sync.aligned.m16n8k16.row.col.f32.bf16.bf16.f32 "               \
        "{%0,%1,%2,%3}, {%4,%5,%6,%7}, {%8,%9}, {%0,%1,%2,%3};"              \
        : "+f"(d[0]), "+f"(d[1]), "+f"(d[2]), "+f"(d[3])                     \
        : "r"(a0), "r"(a1), "r"(a2), "r"(a3), "r"(b0), "r"(b1))

// ---------------- weight pre-pack: W[K,N] fp32 -> hi/lo bf16x2 k-pairs ----------------
__global__ void pack_w_kernel(const float* __restrict__ W,
                              uint32_t* __restrict__ WH, uint32_t* __restrict__ WL,
                              int N, int total) {
    int i = blockIdx.x * blockDim.x + threadIdx.x;
    if (i >= total) return;
    int k2 = i / N, n = i - k2 * N;
    split_pair(W[(size_t)(2 * k2) * N + n], W[(size_t)(2 * k2 + 1) * N + n], WH[i], WL[i]);
}

// ---------------- ray setup ----------------
__global__ void ray_setup_kernel(const float* __restrict__ rd) {
    int r = blockIdx.x * blockDim.x + threadIdx.x;
    if (r >= NRAYS) return;
    float x = rd[r * 3 + 0], y = rd[r * 3 + 1], z = rd[r * 3 + 2];
    float n = sqrtf(x * x + y * y + z * z);
    g_raynorm[r] = n;
    float inv = 1.0f / n;
    float v[3] = {x * inv, y * inv, z * inv};
    float* de = g_direnc + r * 27;
    de[0] = v[0]; de[1] = v[1]; de[2] = v[2];
#pragma unroll
    for (int f = 0; f < 4; f++) {
        float fr = (float)(1 << f);
#pragma unroll
        for (int k = 0; k < 3; k++) {
            float xx = v[k] * fr;
            de[3 + f * 3 + k]  = sinf(xx);
            de[15 + f * 3 + k] = cosf(xx);
        }
    }
}

// per-ray bias for Wd layer: bd[o] + sum_j direnc[j] * Wd[256+j][o]
__global__ void ray_bias_kernel(const float* __restrict__ Wd, const float* __restrict__ bd) {
    int r = blockIdx.x;
    int o = threadIdx.x;
    __shared__ float de[27];
    if (o < 27) de[o] = g_direnc[r * 27 + o];
    __syncthreads();
    float a = bd[o];
#pragma unroll
    for (int j = 0; j < 27; j++) a += de[j] * Wd[(256 + j) * 128 + o];
    g_raybias[r * 128 + o] = a;
}

// ---------------- IPE, block-transposed output [ray][k][m] ----------------
__global__ void ipe_kernel(const float* __restrict__ ro, const float* __restrict__ rd,
                           const float* __restrict__ rr, const float* __restrict__ tsrc) {
    int s = blockIdx.x * blockDim.x + threadIdx.x;
    if (s >= NS) return;
    int ray = s >> 7, i = s & 127;
    float t0, t1;
    if (tsrc) {
        t0 = tsrc[ray * 129 + i];
        t1 = tsrc[ray * 129 + i + 1];
    } else {
        t0 = 2.0f + 4.0f * ((float)i / 128.0f);
        t1 = 2.0f + 4.0f * ((float)(i + 1) / 128.0f);
    }
    float c  = 0.5f * (t0 + t1);
    float dd = 0.5f * (t1 - t0);
    float d2s = dd * dd;
    float d4  = d2s * d2s;
    float c2  = c * c;
    float denom = 3.0f * c2 + d2s;
    float t_mean = c + 2.0f * c * d2s / denom;
    float t_var  = d2s * (1.0f / 3.0f) - (4.0f / 15.0f) * (d4 * (12.0f * c2 - d2s)) / (denom * denom);
    float rrv = rr[ray];
    float r_var = rrv * rrv * (c2 * 0.25f + (5.0f / 12.0f) * d2s - (4.0f / 15.0f) * d4 / denom);

    float rdv[3] = {rd[ray * 3 + 0], rd[ray * 3 + 1], rd[ray * 3 + 2]};
    float rov[3] = {ro[ray * 3 + 0], ro[ray * 3 + 1], ro[ray * 3 + 2]};
    float dn2 = rdv[0] * rdv[0] + rdv[1] * rdv[1] + rdv[2] * rdv[2];
    float invd2 = 1.0f / fmaxf(dn2, 1e-10f);
    float mean[3], cov[3];
#pragma unroll
    for (int k = 0; k < 3; k++) {
        mean[k] = rov[k] + rdv[k] * t_mean;
        float dok = rdv[k] * rdv[k];
        cov[k] = t_var * dok + r_var * (1.0f - dok * invd2);
    }

    float* e = g_enc + (size_t)ray * 96 * 128;
    int m = i;
    float scale = 1.0f;
#pragma unroll 4
    for (int deg = 0; deg < 16; deg++) {
        float sc2 = scale * scale;
#pragma unroll
        for (int k = 0; k < 3; k++) {
            int idx = deg * 3 + k;
            float sv, cv;
            float yv = cov[k] * sc2;
            if (yv > 60.0f) {
                sv = 0.0f; cv = 0.0f;
            } else {
                float att = __expf(-0.5f * yv);
                float y = mean[k] * scale;
                double kd = rint((double)y * 0.15915494309189535);
                float rp = (float)((double)y - kd * 6.283185307179586);
                sv = __sinf(rp) * att;
                cv = __cosf(rp) * att;
            }
            e[(size_t)idx * 128 + m]        = sv;
            e[(size_t)(48 + idx) * 128 + m] = cv;
        }
        scale *= 2.0f;
    }
}

// ---------------- fused-MLP layer, bf16x3 m16n8k16, cp.async W pipeline ----------------
// 512 threads, 16 warps as 8(m) x 2(n); warp tile m16 x (NT*8). N total = NT*16.
// act[k][m] raw fp32, stride 132; A split to bf16 hi/lo at fragment load.
// W pre-packed (hi/lo bf16x2 k-pairs) in global; streamed via 3-buffer cp.async.
template<int NT, bool RELU>
__device__ __forceinline__ void run_layer(
    float* __restrict__ act, uint32_t* __restrict__ BbH, uint32_t* __restrict__ BbL,
    const uint32_t* __restrict__ WH, const uint32_t* __restrict__ WL,
    const float* __restrict__ bias,
    int K, int tid, int wid, int lane)
{
    constexpr int NCOLS = NT * 16;
    constexpr int WPT = NCOLS / 64;          // u32 words per thread per array (4 or 2)
    const int wm = (wid & 7) * 16;
    const int wn = (wid >> 3) * (NT * 8);
    const int g  = lane >> 2;
    const int t4 = lane & 3;

    const int k2r = tid >> 6;                // 0..7
    const int nnr = (tid & 63) * WPT;
    const int nStage = K >> 4;

    auto issueB = [&](int s) {
        const int b = s % 3;
        const uint32_t* srcH = WH + (size_t)(s * 8 + k2r) * NCOLS + nnr;
        const uint32_t* srcL = WL + (size_t)(s * 8 + k2r) * NCOLS + nnr;
        uint32_t* dstH = BbH + b * 2112 + k2r * 264 + nnr;
        uint32_t* dstL = BbL + b * 2112 + k2r * 264 + nnr;
        if constexpr (WPT == 4) {
            cp16(dstH, srcH);
            cp16(dstL, srcL);
        } else {
            cp8(dstH, srcH);
            cp8(dstL, srcL);
        }
        cp_commit();
    };

    float d[NT][4];
#pragma unroll
    for (int nt = 0; nt < NT; nt++)
#pragma unroll
        for (int q = 0; q < 4; q++) d[nt][q] = 0.0f;

    // prologue: prefetch stages 0 and 1
    issueB(0);
    if (nStage > 1) issueB(1);

    for (int s = 0; s < nStage; ++s) {
        if (s + 1 < nStage) cp_wait1(); else cp_wait0();
        __syncthreads();                     // B[s] visible; buf (s+2)%3 consumers done
        if (s + 2 < nStage) issueB(s + 2);

        // A fragments: k-pairs split to bf16 hi/lo at load
        uint32_t aH[4], aL[4];
        {
            const float* A0 = act + (size_t)(s * 16 + 2 * t4) * ACT_STRIDE;
            const float* A8 = A0 + 8 * ACT_STRIDE;
            const int ma = wm + g, mb = ma + 8;
            split_pair(A0[ma], A0[ACT_STRIDE + ma], aH[0], aL[0]);
            split_pair(A0[mb], A0[ACT_STRIDE + mb], aH[1], aL[1]);
            split_pair(A8[ma], A8[ACT_STRIDE + ma], aH[2], aL[2]);
            split_pair(A8[mb], A8[ACT_STRIDE + mb], aH[3], aL[3]);
        }

        const int buf = s % 3;
        const uint32_t* bh = BbH + buf * 2112 + t4 * 264;
        const uint32_t* bl = BbL + buf * 2112 + t4 * 264;
#pragma unroll
        for (int nt = 0; nt < NT; nt++) {
            const int n0 = wn + nt * 8 + g;
            uint32_t bH0 = bh[n0];
            uint32_t bH1 = bh[4 * 264 + n0];
            uint32_t bL0 = bl[n0];
            uint32_t bL1 = bl[4 * 264 + n0];
            MMA_BF16(d[nt], aH[0], aH[1], aH[2], aH[3], bH0, bH1);
            MMA_BF16(d[nt], aL[0], aL[1], aL[2], aL[3], bH0, bH1);
            MMA_BF16(d[nt], aH[0], aH[1], aH[2], aH[3], bL0, bL1);
        }
    }

    __syncthreads();   // all act reads complete before overwrite

    // transposed epilogue: act[col][row] = activation(value + bias)
#pragma unroll
    for (int nt = 0; nt < NT; nt++) {
        const int c0 = wn + nt * 8 + 2 * t4;
        const int r0 = wm + g;
        float b0v = bias[c0], b1v = bias[c0 + 1];
        float v0 = d[nt][0] + b0v;
        float v1 = d[nt][1] + b1v;
        float v2 = d[nt][2] + b0v;
        float v3 = d[nt][3] + b1v;
        if (RELU) {
            v0 = fmaxf(v0, 0.0f); v1 = fmaxf(v1, 0.0f);
            v2 = fmaxf(v2, 0.0f); v3 = fmaxf(v3, 0.0f);
        }
        act[(size_t)c0 * ACT_STRIDE + r0]           = v0;
        act[(size_t)(c0 + 1) * ACT_STRIDE + r0]     = v1;
        act[(size_t)c0 * ACT_STRIDE + r0 + 8]       = v2;
        act[(size_t)(c0 + 1) * ACT_STRIDE + r0 + 8] = v3;
    }
    __syncthreads();
}

// ---------------- fused MLP: one block = one ray (128 samples) ----------------
template<bool COARSE>
__global__ void __launch_bounds__(512, 1) fused_mlp(
    const float* __restrict__ enc_t,
    const uint32_t* __restrict__ WpkH, const uint32_t* __restrict__ WpkL,
    const float* __restrict__ b0, const float* __restrict__ bh,
    const float* __restrict__ Ws, const float* __restrict__ bs,
    const float* __restrict__ Wm, const float* __restrict__ bm,
    const float* __restrict__ bb,
    const float* __restrict__ rbias_all,
    const float* __restrict__ Wr, const float* __restrict__ br,
    float* __restrict__ RF)
{
    extern __shared__ float smem[];
    float* act = smem;
    uint32_t* BbH = (uint32_t*)(smem + ACT_WORDS);
    uint32_t* BbL = BbH + BPK_WORDS;

    const int tid  = threadIdx.x;
    const int wid  = tid >> 5;
    const int lane = tid & 31;
    const int blk  = blockIdx.x;

    // load enc tile [96][128] into act
    {
        const float* ebase = enc_t + (size_t)blk * 96 * 128;
        for (int i = tid; i < 96 * 32; i += 512) {
            int k = i >> 5, m4 = (i & 31) * 4;
            cp16(act + (size_t)k * ACT_STRIDE + m4, ebase + k * 128 + m4);
        }
        cp_commit(); cp_wait0();
    }
    __syncthreads();

    run_layer<16, true>(act, BbH, BbL, WpkH + OFF_W0, WpkL + OFF_W0, b0, 96, tid, wid, lane);
    for (int l = 0; l < 3; l++)
        run_layer<16, true>(act, BbH, BbL, WpkH + OFF_WH + l * 32768, WpkL + OFF_WH + l * 32768,
                            bh + l * 256, 256, tid, wid, lane);

    // heads from x1 (= act): sigma (+ mu/sig for coarse)
    float* rf = RF + (size_t)blk * 128 * 6;
    if (wid < 4) {
        int m = wid * 32 + lane;
        float s0 = 0.0f, s1 = 0.0f, s2 = 0.0f;
        for (int k = 0; k < 256; k++) {
            float xv = act[(size_t)k * ACT_STRIDE + m];
            s0 += xv * __ldg(Ws + k);
            if (COARSE) {
                s1 += xv * __ldg(Wm + 2 * k);
                s2 += xv * __ldg(Wm + 2 * k + 1);
            }
        }
        rf[m * 6 + 3] = s0 + __ldg(bs);
        if (COARSE) {
            rf[m * 6 + 4] = s1 + __ldg(bm);
            rf[m * 6 + 5] = s2 + __ldg(bm + 1);
        }
    }
    __syncthreads();

    run_layer<16, false>(act, BbH, BbL, WpkH + OFF_WB, WpkL + OFF_WB, bb, 256, tid, wid, lane);
    run_layer<8, true>(act, BbH, BbL, WpkH + OFF_WD, WpkL + OFF_WD,
                       rbias_all + (size_t)blk * 128, 256, tid, wid, lane);

    // rgb head from h (= act rows 0..127)
    if (wid < 4) {
        int m = wid * 32 + lane;
        float r = 0.0f, gg = 0.0f, b = 0.0f;
        for (int k = 0; k < 128; k++) {
            float hv = act[(size_t)k * ACT_STRIDE + m];
            r  += hv * __ldg(Wr + 3 * k);
            gg += hv * __ldg(Wr + 3 * k + 1);
            b  += hv * __ldg(Wr + 3 * k + 2);
        }
        rf[m * 6 + 0] = r  + __ldg(br);
        rf[m * 6 + 1] = gg + __ldg(br + 1);
        rf[m * 6 + 2] = b  + __ldg(br + 2);
    }
}

// ---------------- coarse volume render + PDF ingredients ----------------
__global__ void vrender_coarse_kernel(float* __restrict__ out) {
    int r = blockIdx.x * blockDim.x + threadIdx.x;
    if (r >= NRAYS) return;
    float nrm = g_raynorm[r];
    float T = 1.0f, cr = 0.0f, cg = 0.0f, cb = 0.0f;
    for (int i = 0; i < 128; i++) {
        const float* f = g_rf + (size_t)(r * 128 + i) * 6;
        float t0 = 2.0f + 4.0f * ((float)i / 128.0f);
        float t1 = 2.0f + 4.0f * ((float)(i + 1) / 128.0f);
        float sr = fast_sigmoid(f[0]);
        float sg = fast_sigmoid(f[1]);
        float sb = fast_sigmoid(f[2]);
        float sigma = fmaxf(f[3], 0.0f);
        float alpha = 1.0f - __expf(-sigma * (t1 - t0) * nrm);
        float w = alpha * T;
        T *= (1.0f - alpha + 1e-10f);
        cr += w * sr; cg += w * sg; cb += w * sb;
        int si = r * 128 + i;
        g_weights[si] = w;
        float mu = fast_sigmoid(f[4]);
        float ss = (fast_sigmoid(f[5]) + 0.001f) * 2.0f;
        g_mus[si] = mu;
        g_smsig[si] = ss;
        float l = acdf_((0.0f - mu) / ss);
        g_lt[si] = l;
        g_pib[si] = acdf_((1.0f - mu) / ss) - l;
    }
    out[r * 3 + 0] = cr;
    out[r * 3 + 1] = cg;
    out[r * 3 + 2] = cb;
}

// ---------------- per-ray normalized CDF / PDF ----------------
__global__ void cdf_kernel() {
    int r = blockIdx.x * blockDim.x + threadIdx.x;
    if (r >= NRAYS) return;
    float sum = 0.0f;
    for (int i = 0; i < 128; i++) sum += g_weights[r * 128 + i] + 1e-5f;
    float inv = 1.0f / sum;
    g_cdf[r * 129] = 0.0f;
    float run = 0.0f;
    for (int i = 0; i < 128; i++) {
        float w = (g_weights[r * 128 + i] + 1e-5f) * inv;
        g_pdfn[r * 128 + i] = w;
        run += w;
        g_cdf[r * 129 + i + 1] = run;
    }
}

// ---------------- parallel inverse-CDF fine sampling ----------------
__global__ void fine_sample_kernel() {
    int t = blockIdx.x * blockDim.x + threadIdx.x;
    if (t >= NRAYS * 129) return;
    int r = t / 129;
    int i = t - r * 129;
    const float step = (1.0f - 1e-5f) / 128.0f;
    float u = step * (float)i;
    const float* cdf = g_cdf + r * 129;
    int lo = 0, hi = 128;
    while (lo < hi) {
        int mid = (lo + hi + 1) >> 1;
        if (cdf[mid] <= u) lo = mid; else hi = mid - 1;
    }
    int idx = lo < 127 ? lo : 127;
    float pdfv = g_pdfn[r * 128 + idx];
    float frac = (u - cdf[idx]) / fmaxf(pdfv, 1e-10f);
    frac = fminf(fmaxf(frac, 0.0f), 1.0f);
    int si = r * 128 + idx;
    float p = g_lt[si] + frac * g_pib[si];
    p = fminf(fmaxf(p, 1e-5f), 1.0f - 1e-5f);
    float x = g_mus[si] + g_smsig[si] * 1.4142135623730951f * erfinvf(2.0f * p - 1.0f);
    x = fminf(fmaxf(x, 0.0f), 1.0f);
    float b0 = 2.0f + 4.0f * ((float)idx / 128.0f);
    float b1 = 2.0f + 4.0f * ((float)(idx + 1) / 128.0f);
    g_tfine[r * 129 + i] = b0 + x * (b1 - b0);
}

// ---------------- fine volume render ----------------
__global__ void vrender_fine_kernel(float* __restrict__ out) {
    int r = blockIdx.x * blockDim.x + threadIdx.x;
    if (r >= NRAYS) return;
    float nrm = g_raynorm[r];
    float T = 1.0f, cr = 0.0f, cg = 0.0f, cb = 0.0f, dep = 0.0f, acc = 0.0f;
    for (int i = 0; i < 128; i++) {
        const float* f = g_rf + (size_t)(r * 128 + i) * 6;
        float t0 = g_tfine[r * 129 + i];
        float t1 = g_tfine[r * 129 + i + 1];
        float sr = fast_sigmoid(f[0]);
        float sg = fast_sigmoid(f[1]);
        float sb = fast_sigmoid(f[2]);
        float sigma = fmaxf(f[3], 0.0f);
        float alpha = 1.0f - __expf(-sigma * (t1 - t0) * nrm);
        float w = alpha * T;
        T *= (1.0f - alpha + 1e-10f);
        cr += w * sr; cg += w * sg; cb += w * sb;
        dep += w * 0.5f * (t0 + t1);
        acc += w;
    }
    out[6144 + r * 3 + 0] = cr;
    out[6144 + r * 3 + 1] = cg;
    out[6144 + r * 3 + 2] = cb;
    out[12288 + r] = dep;
    out[14336 + r] = acc;
}

// ---------------- host orchestration ----------------
extern "C" void kernel_launch(void* const* d_in, const int* in_sizes, int n_in,
                              void* d_out, int out_size)
{
    (void)out_size;
    const float* ro = (const float*)d_in[0];
    const float* rd = (const float*)d_in[1];
    const float* rr = (const float*)d_in[2];

    bool sigOrder = (n_in > 15 && in_sizes[15] == 512);
    int fb = sigOrder ? 17 : 15;
    int mb = sigOrder ? 15 : 27;

    const float* cW0 = (const float*)d_in[3];
    const float* cb0 = (const float*)d_in[4];
    const float* cWh = (const float*)d_in[5];
    const float* cbh = (const float*)d_in[6];
    const float* cWs = (const float*)d_in[7];
    const float* cbs = (const float*)d_in[8];
    const float* cWb = (const float*)d_in[9];
    const float* cbb = (const float*)d_in[10];
    const float* cWd = (const float*)d_in[11];
    const float* cbd = (const float*)d_in[12];
    const float* cWr = (const float*)d_in[13];
    const float* cbr = (const float*)d_in[14];
    const float* cWm = (const float*)d_in[mb];
    const float* cbm = (const float*)d_in[mb + 1];
    const float* fW0 = (const float*)d_in[fb + 0];
    const float* fb0 = (const float*)d_in[fb + 1];
    const float* fWh = (const float*)d_in[fb + 2];
    const float* fbh = (const float*)d_in[fb + 3];
    const float* fWs = (const float*)d_in[fb + 4];
    const float* fbs = (const float*)d_in[fb + 5];
    const float* fWb = (const float*)d_in[fb + 6];
    const float* fbb = (const float*)d_in[fb + 7];
    const float* fWd = (const float*)d_in[fb + 8];
    const float* fbd = (const float*)d_in[fb + 9];
    const float* fWr = (const float*)d_in[fb + 10];
    const float* fbr = (const float*)d_in[fb + 11];

    float *p_enc, *p_rf, *p_raybias, *p_tfine;
    cudaGetSymbolAddress((void**)&p_enc, g_enc);
    cudaGetSymbolAddress((void**)&p_rf, g_rf);
    cudaGetSymbolAddress((void**)&p_raybias, g_raybias);
    cudaGetSymbolAddress((void**)&p_tfine, g_tfine);
    uint32_t *pH, *pL;
    cudaGetSymbolAddress((void**)&pH, g_wpkH);
    cudaGetSymbolAddress((void**)&pL, g_wpkL);

    cudaFuncSetAttribute(fused_mlp<true>,  cudaFuncAttributeMaxDynamicSharedMemorySize, FUSED_SMEM);
    cudaFuncSetAttribute(fused_mlp<false>, cudaFuncAttributeMaxDynamicSharedMemorySize, FUSED_SMEM);

    float* out = (float*)d_out;

    // ---- pre-pack all weights (both networks) ----
    {
        const float* W0s[2] = {cW0, fW0};
        const float* Whs[2] = {cWh, fWh};
        const float* Wbs[2] = {cWb, fWb};
        const float* Wds[2] = {cWd, fWd};
        for (int net = 0; net < 2; net++) {
            uint32_t* H = pH + net * WPK_TOTAL;
            uint32_t* L = pL + net * WPK_TOTAL;
            pack_w_kernel<<<(12288 + 255) / 256, 256>>>(W0s[net], H + OFF_W0, L + OFF_W0, 256, 12288);
            for (int l = 0; l < 3; l++)
                pack_w_kernel<<<(32768 + 255) / 256, 256>>>(Whs[net] + l * 65536,
                    H + OFF_WH + l * 32768, L + OFF_WH + l * 32768, 256, 32768);
            pack_w_kernel<<<(32768 + 255) / 256, 256>>>(Wbs[net], H + OFF_WB, L + OFF_WB, 256, 32768);
            pack_w_kernel<<<(16384 + 255) / 256, 256>>>(Wds[net], H + OFF_WD, L + OFF_WD, 128, 16384);
        }
    }

    ray_setup_kernel<<<(NRAYS + 127) / 128, 128>>>(rd);

    // ================= coarse pass =================
    ipe_kernel<<<NS / 128, 128>>>(ro, rd, rr, nullptr);
    ray_bias_kernel<<<NRAYS, 128>>>(cWd, cbd);
    fused_mlp<true><<<NRAYS, 512, FUSED_SMEM>>>(
        p_enc, pH, pL, cb0, cbh, cWs, cbs, cWm, cbm, cbb,
        p_raybias, cWr, cbr, p_rf);
    vrender_coarse_kernel<<<(NRAYS + 127) / 128, 128>>>(out);
    cdf_kernel<<<(NRAYS + 127) / 128, 128>>>();
    fine_sample_kernel<<<(NRAYS * 129 + 255) / 256, 256>>>();

    // ================= fine pass =================
    ipe_kernel<<<NS / 128, 128>>>(ro, rd, rr, p_tfine);
    ray_bias_kernel<<<NRAYS, 128>>>(fWd, fbd);
    fused_mlp<false><<<NRAYS, 512, FUSED_SMEM>>>(
        p_enc, pH + WPK_TOTAL, pL + WPK_TOTAL, fb0, fbh, fWs, fbs, nullptr, nullptr, fbb,
        p_raybias, fWr, fbr, p_rf);
    vrender_fine_kernel<<<(NRAYS + 127) / 128, 128>>>(out);
}